// round 13
// baseline (speedup 1.0000x reference)
#include <cuda_runtime.h>
#include <cuda_fp16.h>
#include <cstdint>

// Problem constants
#define Bd  8
#define Sd  1024
#define Hd  1024
#define NHd 16
#define KQd 512
#define HDd 64

#define LOG2E 1.4426950408889634f
#define ONES_H2 0x3C003C00u

// Scratch (device globals: no allocation allowed in kernel_launch)
__device__ int    g_idx[Bd * KQd];
__device__ __half g_h16[Bd * Sd * Hd];        // hidden fp16
__device__ __half g_wq16[Hd * Hd];
__device__ __half g_wk16[Hd * Hd];
__device__ __half g_wv16[Hd * Hd];
__device__ __half g_q16[Bd * NHd * KQd * HDd];   // [B,NH,K,HD]  (pre-scaled)
__device__ __half g_k16[Bd * NHd * Sd  * HDd];   // [B,NH,S,HD]
__device__ __half g_v16[Bd * NHd * Sd  * HDd];   // [B,NH,S,HD]

// ---------------------------------------------------------------------------
// helpers
// ---------------------------------------------------------------------------
__device__ __forceinline__ uint32_t smem_u32(const void* p) {
    uint32_t a;
    asm("{ .reg .u64 t; cvta.to.shared.u64 t, %1; cvt.u32.u64 %0, t; }"
        : "=r"(a) : "l"(p));
    return a;
}

__device__ __forceinline__ void ldsm_x4(uint32_t& r0, uint32_t& r1,
                                        uint32_t& r2, uint32_t& r3, uint32_t addr) {
    asm volatile("ldmatrix.sync.aligned.m8n8.x4.shared.b16 {%0,%1,%2,%3}, [%4];"
                 : "=r"(r0), "=r"(r1), "=r"(r2), "=r"(r3) : "r"(addr));
}
__device__ __forceinline__ void ldsm_x4_t(uint32_t& r0, uint32_t& r1,
                                          uint32_t& r2, uint32_t& r3, uint32_t addr) {
    asm volatile("ldmatrix.sync.aligned.m8n8.x4.trans.shared.b16 {%0,%1,%2,%3}, [%4];"
                 : "=r"(r0), "=r"(r1), "=r"(r2), "=r"(r3) : "r"(addr));
}

__device__ __forceinline__ void mma_f16(float* d, const uint32_t* a,
                                        uint32_t b0, uint32_t b1) {
    asm volatile(
        "mma.sync.aligned.m16n8k16.row.col.f32.f16.f16.f32 "
        "{%0,%1,%2,%3}, {%4,%5,%6,%7}, {%8,%9}, {%0,%1,%2,%3};\n"
        : "+f"(d[0]), "+f"(d[1]), "+f"(d[2]), "+f"(d[3])
        : "r"(a[0]), "r"(a[1]), "r"(a[2]), "r"(a[3]), "r"(b0), "r"(b1));
}

__device__ __forceinline__ uint32_t pack_h2(float lo, float hi) {
    __half2 h = __floats2half2_rn(lo, hi);
    return *reinterpret_cast<uint32_t*>(&h);
}

// two probs per MUFU op: exp2 of packed half2
__device__ __forceinline__ uint32_t ex2_h2(uint32_t x) {
    uint32_t r;
    asm("ex2.approx.f16x2 %0, %1;" : "=r"(r) : "r"(x));
    return r;
}

__device__ __forceinline__ void cp16(uint32_t saddr, const void* gaddr, int srcsz) {
    asm volatile("cp.async.cg.shared.global [%0], [%1], 16, %2;\n"
                 :: "r"(saddr), "l"(gaddr), "r"(srcsz));
}
__device__ __forceinline__ void cp_commit() {
    asm volatile("cp.async.commit_group;\n");
}
template <int N>
__device__ __forceinline__ void cp_wait() {
    asm volatile("cp.async.wait_group %0;\n" :: "n"(N));
}

// ---------------------------------------------------------------------------
// Kernel 0+1 fused: blocks 0..7 build gather indices (1024-thread scan);
// remaining blocks convert hidden + weights to fp16 (4 float4s per thread).
// ---------------------------------------------------------------------------
#define N4H (Bd * Sd * Hd / 4)
#define N4W (Hd * Hd / 4)
#define NCVT (N4H + 3 * N4W)              // 2,883,584 float4s
#define CVT_BLOCKS (NCVT / 4096)          // 704 (each block does 4096 float4s)
#define INIT_GRID (8 + CVT_BLOCKS)

__global__ void __launch_bounds__(1024) init_kernel(
    const int* __restrict__ remain,
    const float* __restrict__ hidden,
    const float* __restrict__ Wq,
    const float* __restrict__ Wk,
    const float* __restrict__ Wv)
{
    if (blockIdx.x < 8) {
        // ---- select: stable compaction of remain==1 positions ----
        __shared__ int sc[Sd];
        int b = blockIdx.x;
        int t = threadIdx.x;
        int r = remain[b * Sd + t];
        sc[t] = r;
        __syncthreads();
        for (int off = 1; off < Sd; off <<= 1) {
            int v = (t >= off) ? sc[t - off] : 0;
            __syncthreads();
            sc[t] += v;
            __syncthreads();
        }
        if (t < KQd) g_idx[b * KQd + t] = -1;
        __syncthreads();
        if (r) {
            int pos = sc[t] - 1;
            if (pos < KQd) g_idx[b * KQd + pos] = t;
        }
        return;
    }
    // ---- cvt: four coalesced float4s per thread (MLP=4) ----
    int base = (blockIdx.x - 8) * 4096 + threadIdx.x;
#pragma unroll
    for (int u = 0; u < 4; u++) {
        int i = base + u * 1024;
        const float4* src;
        __half* dst;
        int j;
        if (i < N4H)                { src = (const float4*)hidden; dst = g_h16;  j = i; }
        else if (i < N4H + N4W)     { src = (const float4*)Wq;     dst = g_wq16; j = i - N4H; }
        else if (i < N4H + 2 * N4W) { src = (const float4*)Wk;     dst = g_wk16; j = i - N4H - N4W; }
        else                        { src = (const float4*)Wv;     dst = g_wv16; j = i - N4H - 2 * N4W; }
        float4 v = src[j];
        __half2* d2 = (__half2*)(dst + 4 * (size_t)j);
        d2[0] = __floats2half2_rn(v.x, v.y);
        d2[1] = __floats2half2_rn(v.z, v.w);
    }
}

// ---------------------------------------------------------------------------
// Kernel 2: merged Q/K/V projection GEMM, fp16 mma.m16n8k16 + ldmatrix.
// CTA tile 128m x 256n, 512 threads (16 warps = 4m x 4n, warp tile 32x64),
// k-chunks of 64, 3-stage cp.async ring, copy after compute (R8 schedule).
// Q output is pre-scaled by 0.125*log2(e) (softmax exponent prefold).
// ---------------------------------------------------------------------------
#define SA_B   144                 // smem row stride bytes (128B data + 16 pad)
#define A_STG  (128 * SA_B)        // 18432 (A: 128 rows)
#define B_STG  (256 * SA_B)        // 36864 (B: 256 rows)
#define STG    (A_STG + B_STG)     // 55296 per stage
#define GEMM_SMEM (3 * STG)        // 165888 bytes
#define KCHUNKS 16                 // 1024 / 64
#define TN 256

__global__ void __launch_bounds__(512, 1) gemm_qkv_f16(
    const float* __restrict__ bq, const float* __restrict__ bk,
    const float* __restrict__ bv)
{
    extern __shared__ __align__(16) uint8_t dsm[];
    uint32_t sbase = smem_u32(dsm);

    int x = blockIdx.x;
    const __half* W; const float* bias; __half* outp; int M, which, mt0;
    if (x < 4)       { which = 0; mt0 = x;      W = g_wq16; bias = bq; outp = g_q16; M = KQd; }
    else if (x < 12) { which = 1; mt0 = x - 4;  W = g_wk16; bias = bk; outp = g_k16; M = Sd;  }
    else             { which = 2; mt0 = x - 12; W = g_wv16; bias = bv; outp = g_v16; M = Sd;  }

    int b    = blockIdx.z;
    int m0   = mt0 * 128;
    int n0   = blockIdx.y * TN;
    int tid  = threadIdx.x;
    int lane = tid & 31;
    int warp = tid >> 5;
    int wm = warp >> 2;          // 0..3 -> m offset wm*32
    int wn = warp & 3;           // 0..3 -> n offset wn*64
    int g  = lane >> 2;
    int t  = lane & 3;

    // staging: 512 threads; row group tid>>3 (0..63), chunk c = tid&7
    int srow = tid >> 3;         // 0..63
    int c    = tid & 7;          // 16B chunk within 128B row

    const __half* xb = g_h16 + (size_t)b * Sd * Hd;
    const __half* aptr[2]; int asz[2];
    const __half* bptr[4];
#pragma unroll
    for (int u = 0; u < 2; u++) {
        int r = srow + 64 * u;   // A rows 0..127
        int src = (which == 0) ? g_idx[b * KQd + m0 + r] : (m0 + r);
        asz[u]  = (src >= 0) ? 16 : 0;
        aptr[u] = xb + (size_t)(src < 0 ? 0 : src) * Hd + c * 8;
    }
#pragma unroll
    for (int u = 0; u < 4; u++) {
        int r = srow + 64 * u;   // B rows 0..255
        bptr[u] = W + (size_t)(n0 + r) * Hd + c * 8;
    }
    uint32_t dA[2], dB[4];
#pragma unroll
    for (int u = 0; u < 2; u++)
        dA[u] = sbase + (uint32_t)((srow + 64 * u) * SA_B + c * 16);
#pragma unroll
    for (int u = 0; u < 4; u++)
        dB[u] = sbase + (uint32_t)(A_STG + (srow + 64 * u) * SA_B + c * 16);

    float acc[2][8][4];
#pragma unroll
    for (int mt = 0; mt < 2; mt++)
#pragma unroll
        for (int nt = 0; nt < 8; nt++)
#pragma unroll
            for (int cc = 0; cc < 4; cc++) acc[mt][nt][cc] = 0.f;

    int arow = ((lane & 8) ? 8 : 0) + (lane & 7);
    int kq   = (lane & 16) ? 16 : 0;
    int brow = ((lane & 16) ? 8 : 0) + (lane & 7);
    int bkq  = (lane & 8) ? 16 : 0;

    // prologue: chunks 0,1 -> slots 0,1
#pragma unroll
    for (int u = 0; u < 2; u++) cp16(dA[u], aptr[u], asz[u]);
#pragma unroll
    for (int u = 0; u < 4; u++) cp16(dB[u], bptr[u], 16);
    cp_commit();
#pragma unroll
    for (int u = 0; u < 2; u++) cp16(dA[u] + STG, aptr[u] + 64, asz[u]);
#pragma unroll
    for (int u = 0; u < 4; u++) cp16(dB[u] + STG, bptr[u] + 64, 16);
    cp_commit();

    for (int s = 0; s < KCHUNKS; s++) {
        cp_wait<1>();        // chunk s landed
        __syncthreads();     // visibility + slot (s+2)%3 readers done

        uint32_t Ab = sbase + (uint32_t)((s % 3) * STG);
        uint32_t Bb = Ab + A_STG;

#pragma unroll
        for (int kk = 0; kk < 4; kk++) {
            uint32_t af[2][4];
#pragma unroll
            for (int mt = 0; mt < 2; mt++)
                ldsm_x4(af[mt][0], af[mt][1], af[mt][2], af[mt][3],
                        Ab + (uint32_t)((wm * 32 + mt * 16 + arow) * SA_B + kk * 32 + kq));
            uint32_t bf[8][2];
#pragma unroll
            for (int p = 0; p < 4; p++) {
                uint32_t r0, r1, r2, r3;
                ldsm_x4(r0, r1, r2, r3,
                        Bb + (uint32_t)((wn * 64 + p * 16 + brow) * SA_B + kk * 32 + bkq));
                bf[2 * p][0] = r0; bf[2 * p][1] = r1;
                bf[2 * p + 1][0] = r2; bf[2 * p + 1][1] = r3;
            }
#pragma unroll
            for (int mt = 0; mt < 2; mt++)
#pragma unroll
                for (int nt = 0; nt < 8; nt++)
                    mma_f16(acc[mt][nt], af[mt], bf[nt][0], bf[nt][1]);
        }

        if (s + 2 < KCHUNKS) {
            uint32_t bo = (uint32_t)(((s + 2) % 3) * STG);
            int ko = (s + 2) * 64;
#pragma unroll
            for (int u = 0; u < 2; u++) cp16(dA[u] + bo, aptr[u] + ko, asz[u]);
#pragma unroll
            for (int u = 0; u < 4; u++) cp16(dB[u] + bo, bptr[u] + ko, 16);
        }
        cp_commit();
    }

    // epilogue: bias (fp32), optional softmax prefold scale for Q, store fp16
    float oscale = (which == 0) ? (0.125f * LOG2E) : 1.0f;
#pragma unroll
    for (int nt = 0; nt < 8; nt++) {
        int o    = n0 + wn * 64 + nt * 8 + 2 * t;
        int head = o >> 6;
        int hd   = o & 63;
        float b0 = __ldg(&bias[o]);
        float b1 = __ldg(&bias[o + 1]);
        size_t obase = ((size_t)(b * NHd + head) * M) * HDd + hd;
#pragma unroll
        for (int mt = 0; mt < 2; mt++) {
            int m = m0 + wm * 32 + mt * 16 + g;
            *(__half2*)&outp[obase + (size_t)m * HDd] =
                __floats2half2_rn((acc[mt][nt][0] + b0) * oscale,
                                  (acc[mt][nt][1] + b1) * oscale);
            *(__half2*)&outp[obase + (size_t)(m + 8) * HDd] =
                __floats2half2_rn((acc[mt][nt][2] + b0) * oscale,
                                  (acc[mt][nt][3] + b1) * oscale);
        }
    }
}

// ---------------------------------------------------------------------------
// Kernel 3: fp16 flash attention (R8-proven structure), no-max ex2.f16x2
// softmax, HMMA row sums, register-resident P, 2-stage cp.async K/V.
// Block = (b, h, 64 q-rows), 128 threads (4 warps, 16 q-rows each).
// ---------------------------------------------------------------------------
#define KV_B    144                 // smem row stride bytes
#define KV_STG  (64 * KV_B)         // 9216
#define STAGE_B (2 * KV_STG)        // 18432
#define ATT_SMEM (2 * STAGE_B + Sd * 4)   // 40960

__global__ void __launch_bounds__(128, 4) attn_f16(
    const float* __restrict__ mask, float* __restrict__ out)
{
    extern __shared__ __align__(16) uint8_t asm_[];
    float* msk = (float*)(asm_ + 2 * STAGE_B);
    uint32_t sb = smem_u32(asm_);

    int q0 = blockIdx.x * 64;
    int h  = blockIdx.y;
    int b  = blockIdx.z;
    int tid = threadIdx.x;
    int lane = tid & 31;
    int w = tid >> 5;
    int g = lane >> 2;
    int t = lane & 3;

    const __half* qb = g_q16 + (size_t)(b * NHd + h) * KQd * HDd;
    const __half* kb = g_k16 + (size_t)(b * NHd + h) * Sd  * HDd;
    const __half* vb = g_v16 + (size_t)(b * NHd + h) * Sd  * HDd;
    const float* mrow = mask + (size_t)b * Sd;

    int arow = ((lane & 8) ? 8 : 0) + (lane & 7);
    int akq  = (lane & 16) ? 16 : 0;
    int brow = ((lane & 16) ? 8 : 0) + (lane & 7);
    int bkq  = (lane & 8) ? 16 : 0;
    int vrow = ((lane & 8) ? 8 : 0) + (lane & 7);
    int vkq  = (lane & 16) ? 16 : 0;

    // ---- preload full mask (scaled by log2e) + stage Q into stage0 K area ----
#pragma unroll
    for (int u = 0; u < 2; u++) {
        int idx = tid + u * 128;
        float4 m4 = *(const float4*)(mrow + idx * 4);
        m4.x *= LOG2E; m4.y *= LOG2E; m4.z *= LOG2E; m4.w *= LOG2E;
        *(float4*)&msk[idx * 4] = m4;
    }
#pragma unroll
    for (int u = 0; u < 4; u++) {
        int i = tid + u * 128;
        int r = i >> 3;
        int c = i & 7;
        *(uint4*)(asm_ + r * KV_B + c * 16) =
            *(const uint4*)(qb + (size_t)(q0 + r) * HDd + c * 8);
    }
    __syncthreads();

    uint32_t qf[4][4];
#pragma unroll
    for (int kk = 0; kk < 4; kk++)
        ldsm_x4(qf[kk][0], qf[kk][1], qf[kk][2], qf[kk][3],
                sb + (uint32_t)((w * 16 + arow) * KV_B + kk * 32 + akq));
    __syncthreads();

    // ---- prologue: issue K/V tile 0 into stage 0 ----
#pragma unroll
    for (int u = 0; u < 4; u++) {
        int i = tid + u * 128;
        int r = i >> 3;
        int c = i & 7;
        uint32_t off = (uint32_t)(r * KV_B + c * 16);
        cp16(sb + off,          kb + (size_t)r * HDd + c * 8, 16);
        cp16(sb + KV_STG + off, vb + (size_t)r * HDd + c * 8, 16);
    }
    cp_commit();

    float ls[4] = {0.f, 0.f, 0.f, 0.f};   // HMMA row sums
    float oacc[8][4];
#pragma unroll
    for (int nt = 0; nt < 8; nt++)
#pragma unroll
        for (int cc = 0; cc < 4; cc++) oacc[nt][cc] = 0.f;

    for (int t16 = 0; t16 < 16; t16++) {
        __syncthreads();                  // readers of stage (t16+1)&1 done
        if (t16 + 1 < 16) {
            uint32_t so = (uint32_t)(((t16 + 1) & 1) * STAGE_B);
            int s1 = (t16 + 1) * 64;
#pragma unroll
            for (int u = 0; u < 4; u++) {
                int i = tid + u * 128;
                int r = i >> 3;
                int c = i & 7;
                uint32_t off = so + (uint32_t)(r * KV_B + c * 16);
                cp16(sb + off,          kb + (size_t)(s1 + r) * HDd + c * 8, 16);
                cp16(sb + KV_STG + off, vb + (size_t)(s1 + r) * HDd + c * 8, 16);
            }
        }
        cp_commit();
        cp_wait<1>();                      // tile t16 landed
        __syncthreads();

        uint32_t KsB = sb + (uint32_t)((t16 & 1) * STAGE_B);
        uint32_t VsB = KsB + KV_STG;

        // ---- scores = Q' @ K^T (Q pre-scaled by 0.125*log2e) ----
        float sc[8][4];
#pragma unroll
        for (int nt = 0; nt < 8; nt++)
#pragma unroll
            for (int cc = 0; cc < 4; cc++) sc[nt][cc] = 0.f;

#pragma unroll
        for (int kk = 0; kk < 4; kk++) {
#pragma unroll
            for (int p = 0; p < 4; p++) {
                uint32_t r0, r1, r2, r3;
                ldsm_x4(r0, r1, r2, r3,
                        KsB + (uint32_t)((p * 16 + brow) * KV_B + kk * 32 + bkq));
                mma_f16(sc[2 * p],     qf[kk], r0, r1);
                mma_f16(sc[2 * p + 1], qf[kk], r2, r3);
            }
        }

        // ---- probs: p = 2^(sc + mask'), 2-at-a-time in half2 ----
        const float* mk = msk + t16 * 64;
        uint32_t pa[4][4];
#pragma unroll
        for (int kk = 0; kk < 4; kk++) {
            int n0t = 2 * kk, n1t = 2 * kk + 1;
            float a0 = mk[n0t * 8 + 2 * t], a1 = mk[n0t * 8 + 2 * t + 1];
            float b0 = mk[n1t * 8 + 2 * t], b1 = mk[n1t * 8 + 2 * t + 1];
            pa[kk][0] = ex2_h2(pack_h2(sc[n0t][0] + a0, sc[n0t][1] + a1));
            pa[kk][1] = ex2_h2(pack_h2(sc[n0t][2] + a0, sc[n0t][3] + a1));
            pa[kk][2] = ex2_h2(pack_h2(sc[n1t][0] + b0, sc[n1t][1] + b1));
            pa[kk][3] = ex2_h2(pack_h2(sc[n1t][2] + b0, sc[n1t][3] + b1));
        }

        // ---- row sums via HMMA against ones + oacc += P @ V ----
#pragma unroll
        for (int kk = 0; kk < 4; kk++) {
            mma_f16(ls, pa[kk], ONES_H2, ONES_H2);
#pragma unroll
            for (int p = 0; p < 4; p++) {
                uint32_t r0, r1, r2, r3;
                ldsm_x4_t(r0, r1, r2, r3,
                          VsB + (uint32_t)((kk * 16 + vrow) * KV_B + p * 32 + vkq));
                mma_f16(oacc[2 * p],     pa[kk], r0, r1);
                mma_f16(oacc[2 * p + 1], pa[kk], r2, r3);
            }
        }
    }

    // ---- epilogue (fp32 out) ----
    float iA = 1.f / ls[0];
    float iB = 1.f / ls[2];
    int rA = q0 + w * 16 + g;
#pragma unroll
    for (int nt = 0; nt < 8; nt++) {
        int col = h * 64 + nt * 8 + 2 * t;
        *(float2*)&out[((size_t)b * KQd + rA) * Hd + col] =
            make_float2(oacc[nt][0] * iA, oacc[nt][1] * iA);
        *(float2*)&out[((size_t)b * KQd + rA + 8) * Hd + col] =
            make_float2(oacc[nt][2] * iB, oacc[nt][3] * iB);
    }
}

// ---------------------------------------------------------------------------
extern "C" void kernel_launch(void* const* d_in, const int* in_sizes, int n_in,
                              void* d_out, int out_size)
{
    const float* hidden = (const float*)d_in[0];
    const float* mask   = (const float*)d_in[1];
    const int*   remain = (const int*)d_in[2];
    const float* Wq = (const float*)d_in[3];
    const float* bq = (const float*)d_in[4];
    const float* Wk = (const float*)d_in[5];
    const float* bk = (const float*)d_in[6];
    const float* Wv = (const float*)d_in[7];
    const float* bv = (const float*)d_in[8];
    float* out = (float*)d_out;

    cudaFuncSetAttribute(gemm_qkv_f16,
                         cudaFuncAttributeMaxDynamicSharedMemorySize, GEMM_SMEM);
    cudaFuncSetAttribute(attn_f16,
                         cudaFuncAttributeMaxDynamicSharedMemorySize, ATT_SMEM);

    init_kernel<<<INIT_GRID, 1024>>>(remain, hidden, Wq, Wk, Wv);

    gemm_qkv_f16<<<dim3(20, Hd / TN, Bd), 512, GEMM_SMEM>>>(bq, bk, bv);

    attn_f16<<<dim3(KQd / 64, NHd, Bd), 128, ATT_SMEM>>>(mask, out);
}

// round 14
// speedup vs baseline: 1.0752x; 1.0752x over previous
#include <cuda_runtime.h>
#include <cuda_fp16.h>
#include <cstdint>

// Problem constants
#define Bd  8
#define Sd  1024
#define Hd  1024
#define NHd 16
#define KQd 512
#define HDd 64

#define LOG2E 1.4426950408889634f
#define ONES_H2 0x3C003C00u

// Scratch (device globals: no allocation allowed in kernel_launch)
__device__ int    g_idx[Bd * KQd];
__device__ __half g_h16[Bd * Sd * Hd];        // hidden fp16
__device__ __half g_wq16[Hd * Hd];
__device__ __half g_wk16[Hd * Hd];
__device__ __half g_wv16[Hd * Hd];
__device__ __half g_q16[Bd * NHd * KQd * HDd];   // [B,NH,K,HD]  (pre-scaled)
__device__ __half g_k16[Bd * NHd * Sd  * HDd];   // [B,NH,S,HD]
__device__ __half g_v16[Bd * NHd * Sd  * HDd];   // [B,NH,S,HD]

// ---------------------------------------------------------------------------
// helpers
// ---------------------------------------------------------------------------
__device__ __forceinline__ uint32_t smem_u32(const void* p) {
    uint32_t a;
    asm("{ .reg .u64 t; cvta.to.shared.u64 t, %1; cvt.u32.u64 %0, t; }"
        : "=r"(a) : "l"(p));
    return a;
}

__device__ __forceinline__ void ldsm_x4(uint32_t& r0, uint32_t& r1,
                                        uint32_t& r2, uint32_t& r3, uint32_t addr) {
    asm volatile("ldmatrix.sync.aligned.m8n8.x4.shared.b16 {%0,%1,%2,%3}, [%4];"
                 : "=r"(r0), "=r"(r1), "=r"(r2), "=r"(r3) : "r"(addr));
}
__device__ __forceinline__ void ldsm_x4_t(uint32_t& r0, uint32_t& r1,
                                          uint32_t& r2, uint32_t& r3, uint32_t addr) {
    asm volatile("ldmatrix.sync.aligned.m8n8.x4.trans.shared.b16 {%0,%1,%2,%3}, [%4];"
                 : "=r"(r0), "=r"(r1), "=r"(r2), "=r"(r3) : "r"(addr));
}

__device__ __forceinline__ void mma_f16(float* d, const uint32_t* a,
                                        uint32_t b0, uint32_t b1) {
    asm volatile(
        "mma.sync.aligned.m16n8k16.row.col.f32.f16.f16.f32 "
        "{%0,%1,%2,%3}, {%4,%5,%6,%7}, {%8,%9}, {%0,%1,%2,%3};\n"
        : "+f"(d[0]), "+f"(d[1]), "+f"(d[2]), "+f"(d[3])
        : "r"(a[0]), "r"(a[1]), "r"(a[2]), "r"(a[3]), "r"(b0), "r"(b1));
}

__device__ __forceinline__ uint32_t pack_h2(float lo, float hi) {
    __half2 h = __floats2half2_rn(lo, hi);
    return *reinterpret_cast<uint32_t*>(&h);
}

// two probs per MUFU op: exp2 of packed half2
__device__ __forceinline__ uint32_t ex2_h2(uint32_t x) {
    uint32_t r;
    asm("ex2.approx.f16x2 %0, %1;" : "=r"(r) : "r"(x));
    return r;
}

__device__ __forceinline__ void cp16(uint32_t saddr, const void* gaddr, int srcsz) {
    asm volatile("cp.async.cg.shared.global [%0], [%1], 16, %2;\n"
                 :: "r"(saddr), "l"(gaddr), "r"(srcsz));
}
__device__ __forceinline__ void cp_commit() {
    asm volatile("cp.async.commit_group;\n");
}
template <int N>
__device__ __forceinline__ void cp_wait() {
    asm volatile("cp.async.wait_group %0;\n" :: "n"(N));
}

// ---------------------------------------------------------------------------
// Kernel 0+1 fused: blocks 0..7 build gather indices (1024-thread scan);
// remaining blocks convert to fp16 with coalesced 16B stores.
// Each cvt block covers 4096 consecutive float4s of ONE tensor
// (all tensor sizes divide 4096, so the branch is block-uniform).
// Each thread: 4 consecutive float4 reads (64B) -> 2 uint4 stores (32B).
// ---------------------------------------------------------------------------
#define N4H (Bd * Sd * Hd / 4)            // 2,097,152 float4s
#define N4W (Hd * Hd / 4)                 // 262,144 float4s
#define HBLK (N4H / 4096)                 // 512
#define WBLK (N4W / 4096)                 // 64
#define CVT_BLOCKS (HBLK + 3 * WBLK)      // 704
#define INIT_GRID (8 + CVT_BLOCKS)

__global__ void __launch_bounds__(1024) init_kernel(
    const int* __restrict__ remain,
    const float* __restrict__ hidden,
    const float* __restrict__ Wq,
    const float* __restrict__ Wk,
    const float* __restrict__ Wv)
{
    if (blockIdx.x < 8) {
        // ---- select: stable compaction of remain==1 positions ----
        __shared__ int sc[Sd];
        int b = blockIdx.x;
        int t = threadIdx.x;
        int r = remain[b * Sd + t];
        sc[t] = r;
        __syncthreads();
        for (int off = 1; off < Sd; off <<= 1) {
            int v = (t >= off) ? sc[t - off] : 0;
            __syncthreads();
            sc[t] += v;
            __syncthreads();
        }
        if (t < KQd) g_idx[b * KQd + t] = -1;
        __syncthreads();
        if (r) {
            int pos = sc[t] - 1;
            if (pos < KQd) g_idx[b * KQd + pos] = t;
        }
        return;
    }
    // ---- cvt (block-uniform tensor selection) ----
    int blk = blockIdx.x - 8;
    const float4* src;
    __half* dst;
    if (blk < HBLK)                { src = (const float4*)hidden; dst = g_h16; }
    else if (blk < HBLK + WBLK)    { src = (const float4*)Wq; dst = g_wq16; blk -= HBLK; }
    else if (blk < HBLK + 2*WBLK)  { src = (const float4*)Wk; dst = g_wk16; blk -= HBLK + WBLK; }
    else                           { src = (const float4*)Wv; dst = g_wv16; blk -= HBLK + 2*WBLK; }

    // thread handles float4s j0..j0+3 (consecutive): 64B read, 32B written
    size_t j0 = (size_t)blk * 4096 + (size_t)threadIdx.x * 4;
    float4 v0 = src[j0 + 0];
    float4 v1 = src[j0 + 1];
    float4 v2 = src[j0 + 2];
    float4 v3 = src[j0 + 3];
    uint4 o0, o1;
    o0.x = pack_h2(v0.x, v0.y);  o0.y = pack_h2(v0.z, v0.w);
    o0.z = pack_h2(v1.x, v1.y);  o0.w = pack_h2(v1.z, v1.w);
    o1.x = pack_h2(v2.x, v2.y);  o1.y = pack_h2(v2.z, v2.w);
    o1.z = pack_h2(v3.x, v3.y);  o1.w = pack_h2(v3.z, v3.w);
    uint4* d = (uint4*)(dst + 4 * j0);
    d[0] = o0;
    d[1] = o1;
}

// ---------------------------------------------------------------------------
// Kernel 2: merged Q/K/V projection GEMM, fp16 mma.m16n8k16 + ldmatrix.
// 128x128 tile, 256 threads (8 warps = 4m x 2n), k-chunks of 64,
// 3-stage cp.async ring, copy issued AFTER compute (R8/R11-proven schedule).
// Q output is pre-scaled by 0.125*log2(e) (softmax exponent prefold).
// ---------------------------------------------------------------------------
#define SA_B   144                 // smem row stride bytes (128B data + 16 pad)
#define A_STG  (128 * SA_B)        // 18432
#define STG    (2 * A_STG)         // A + B per stage = 36864
#define GEMM_SMEM (3 * STG)        // 110592 bytes
#define KCHUNKS 16                 // 1024 / 64

__global__ void __launch_bounds__(256, 2) gemm_qkv_f16(
    const float* __restrict__ bq, const float* __restrict__ bk,
    const float* __restrict__ bv)
{
    extern __shared__ __align__(16) uint8_t dsm[];
    uint32_t sbase = smem_u32(dsm);

    int x = blockIdx.x;
    const __half* W; const float* bias; __half* outp; int M, which, mt0;
    if (x < 4)       { which = 0; mt0 = x;      W = g_wq16; bias = bq; outp = g_q16; M = KQd; }
    else if (x < 12) { which = 1; mt0 = x - 4;  W = g_wk16; bias = bk; outp = g_k16; M = Sd;  }
    else             { which = 2; mt0 = x - 12; W = g_wv16; bias = bv; outp = g_v16; M = Sd;  }

    int b    = blockIdx.z;
    int m0   = mt0 * 128;
    int n0   = blockIdx.y * 128;
    int tid  = threadIdx.x;
    int lane = tid & 31;
    int warp = tid >> 5;
    int wm = warp >> 1;
    int wn = warp & 1;
    int g  = lane >> 2;
    int t  = lane & 3;

    int srow = tid >> 3;         // 0..31
    int c    = tid & 7;          // 16B chunk within 128B row

    const __half* xb = g_h16 + (size_t)b * Sd * Hd;
    const __half* aptr[4]; int asz[4];
    const __half* bptr[4];
#pragma unroll
    for (int u = 0; u < 4; u++) {
        int r = srow + 32 * u;   // 0..127
        int src = (which == 0) ? g_idx[b * KQd + m0 + r] : (m0 + r);
        asz[u]  = (src >= 0) ? 16 : 0;
        aptr[u] = xb + (size_t)(src < 0 ? 0 : src) * Hd + c * 8;
        bptr[u] = W  + (size_t)(n0 + r) * Hd + c * 8;
    }
    uint32_t dA[4], dB[4];
#pragma unroll
    for (int u = 0; u < 4; u++) {
        uint32_t off = (uint32_t)((srow + 32 * u) * SA_B + c * 16);
        dA[u] = sbase + off;
        dB[u] = sbase + A_STG + off;
    }

    float acc[2][8][4];
#pragma unroll
    for (int mt = 0; mt < 2; mt++)
#pragma unroll
        for (int nt = 0; nt < 8; nt++)
#pragma unroll
            for (int cc = 0; cc < 4; cc++) acc[mt][nt][cc] = 0.f;

    int arow = ((lane & 8) ? 8 : 0) + (lane & 7);
    int kq   = (lane & 16) ? 16 : 0;
    int brow = ((lane & 16) ? 8 : 0) + (lane & 7);
    int bkq  = (lane & 8) ? 16 : 0;

    // prologue: chunks 0,1 -> slots 0,1
#pragma unroll
    for (int u = 0; u < 4; u++) {
        cp16(dA[u], aptr[u], asz[u]);
        cp16(dB[u], bptr[u], 16);
    }
    cp_commit();
#pragma unroll
    for (int u = 0; u < 4; u++) {
        cp16(dA[u] + STG, aptr[u] + 64, asz[u]);
        cp16(dB[u] + STG, bptr[u] + 64, 16);
    }
    cp_commit();

    for (int s = 0; s < KCHUNKS; s++) {
        cp_wait<1>();        // chunk s landed
        __syncthreads();     // visibility + slot (s+2)%3 readers done

        uint32_t Ab = sbase + (uint32_t)((s % 3) * STG);
        uint32_t Bb = Ab + A_STG;

#pragma unroll
        for (int kk = 0; kk < 4; kk++) {
            uint32_t af[2][4];
#pragma unroll
            for (int mt = 0; mt < 2; mt++)
                ldsm_x4(af[mt][0], af[mt][1], af[mt][2], af[mt][3],
                        Ab + (uint32_t)((wm * 32 + mt * 16 + arow) * SA_B + kk * 32 + kq));
            uint32_t bf[8][2];
#pragma unroll
            for (int p = 0; p < 4; p++) {
                uint32_t r0, r1, r2, r3;
                ldsm_x4(r0, r1, r2, r3,
                        Bb + (uint32_t)((wn * 64 + p * 16 + brow) * SA_B + kk * 32 + bkq));
                bf[2 * p][0] = r0; bf[2 * p][1] = r1;
                bf[2 * p + 1][0] = r2; bf[2 * p + 1][1] = r3;
            }
#pragma unroll
            for (int mt = 0; mt < 2; mt++)
#pragma unroll
                for (int nt = 0; nt < 8; nt++)
                    mma_f16(acc[mt][nt], af[mt], bf[nt][0], bf[nt][1]);
        }

        if (s + 2 < KCHUNKS) {
            uint32_t bo = (uint32_t)(((s + 2) % 3) * STG);
            int ko = (s + 2) * 64;
#pragma unroll
            for (int u = 0; u < 4; u++) {
                cp16(dA[u] + bo, aptr[u] + ko, asz[u]);
                cp16(dB[u] + bo, bptr[u] + ko, 16);
            }
        }
        cp_commit();
    }

    // epilogue: bias (fp32), optional softmax prefold scale for Q, store fp16
    float oscale = (which == 0) ? (0.125f * LOG2E) : 1.0f;
#pragma unroll
    for (int nt = 0; nt < 8; nt++) {
        int o    = n0 + wn * 64 + nt * 8 + 2 * t;
        int head = o >> 6;
        int hd   = o & 63;
        float b0 = __ldg(&bias[o]);
        float b1 = __ldg(&bias[o + 1]);
        size_t obase = ((size_t)(b * NHd + head) * M) * HDd + hd;
#pragma unroll
        for (int mt = 0; mt < 2; mt++) {
            int m = m0 + wm * 32 + mt * 16 + g;
            *(__half2*)&outp[obase + (size_t)m * HDd] =
                __floats2half2_rn((acc[mt][nt][0] + b0) * oscale,
                                  (acc[mt][nt][1] + b1) * oscale);
            *(__half2*)&outp[obase + (size_t)(m + 8) * HDd] =
                __floats2half2_rn((acc[mt][nt][2] + b0) * oscale,
                                  (acc[mt][nt][3] + b1) * oscale);
        }
    }
}

// ---------------------------------------------------------------------------
// Kernel 3: fp16 flash attention (R8/R11-proven), no-max ex2.f16x2 softmax,
// HMMA row sums, register-resident P, 2-stage cp.async K/V.
// Block = (b, h, 64 q-rows), 128 threads (4 warps, 16 q-rows each).
// ---------------------------------------------------------------------------
#define KV_B    144                 // smem row stride bytes
#define KV_STG  (64 * KV_B)         // 9216
#define STAGE_B (2 * KV_STG)        // 18432
#define ATT_SMEM (2 * STAGE_B + Sd * 4)   // 40960

__global__ void __launch_bounds__(128, 4) attn_f16(
    const float* __restrict__ mask, float* __restrict__ out)
{
    extern __shared__ __align__(16) uint8_t asm_[];
    float* msk = (float*)(asm_ + 2 * STAGE_B);
    uint32_t sb = smem_u32(asm_);

    int q0 = blockIdx.x * 64;
    int h  = blockIdx.y;
    int b  = blockIdx.z;
    int tid = threadIdx.x;
    int lane = tid & 31;
    int w = tid >> 5;
    int g = lane >> 2;
    int t = lane & 3;

    const __half* qb = g_q16 + (size_t)(b * NHd + h) * KQd * HDd;
    const __half* kb = g_k16 + (size_t)(b * NHd + h) * Sd  * HDd;
    const __half* vb = g_v16 + (size_t)(b * NHd + h) * Sd  * HDd;
    const float* mrow = mask + (size_t)b * Sd;

    int arow = ((lane & 8) ? 8 : 0) + (lane & 7);
    int akq  = (lane & 16) ? 16 : 0;
    int brow = ((lane & 16) ? 8 : 0) + (lane & 7);
    int bkq  = (lane & 8) ? 16 : 0;
    int vrow = ((lane & 8) ? 8 : 0) + (lane & 7);
    int vkq  = (lane & 16) ? 16 : 0;

    // ---- preload full mask (scaled by log2e) + stage Q into stage0 K area ----
#pragma unroll
    for (int u = 0; u < 2; u++) {
        int idx = tid + u * 128;
        float4 m4 = *(const float4*)(mrow + idx * 4);
        m4.x *= LOG2E; m4.y *= LOG2E; m4.z *= LOG2E; m4.w *= LOG2E;
        *(float4*)&msk[idx * 4] = m4;
    }
#pragma unroll
    for (int u = 0; u < 4; u++) {
        int i = tid + u * 128;
        int r = i >> 3;
        int c = i & 7;
        *(uint4*)(asm_ + r * KV_B + c * 16) =
            *(const uint4*)(qb + (size_t)(q0 + r) * HDd + c * 8);
    }
    __syncthreads();

    uint32_t qf[4][4];
#pragma unroll
    for (int kk = 0; kk < 4; kk++)
        ldsm_x4(qf[kk][0], qf[kk][1], qf[kk][2], qf[kk][3],
                sb + (uint32_t)((w * 16 + arow) * KV_B + kk * 32 + akq));
    __syncthreads();

    // ---- prologue: issue K/V tile 0 into stage 0 ----
#pragma unroll
    for (int u = 0; u < 4; u++) {
        int i = tid + u * 128;
        int r = i >> 3;
        int c = i & 7;
        uint32_t off = (uint32_t)(r * KV_B + c * 16);
        cp16(sb + off,          kb + (size_t)r * HDd + c * 8, 16);
        cp16(sb + KV_STG + off, vb + (size_t)r * HDd + c * 8, 16);
    }
    cp_commit();

    float ls[4] = {0.f, 0.f, 0.f, 0.f};   // HMMA row sums
    float oacc[8][4];
#pragma unroll
    for (int nt = 0; nt < 8; nt++)
#pragma unroll
        for (int cc = 0; cc < 4; cc++) oacc[nt][cc] = 0.f;

    for (int t16 = 0; t16 < 16; t16++) {
        __syncthreads();                  // readers of stage (t16+1)&1 done
        if (t16 + 1 < 16) {
            uint32_t so = (uint32_t)(((t16 + 1) & 1) * STAGE_B);
            int s1 = (t16 + 1) * 64;
#pragma unroll
            for (int u = 0; u < 4; u++) {
                int i = tid + u * 128;
                int r = i >> 3;
                int c = i & 7;
                uint32_t off = so + (uint32_t)(r * KV_B + c * 16);
                cp16(sb + off,          kb + (size_t)(s1 + r) * HDd + c * 8, 16);
                cp16(sb + KV_STG + off, vb + (size_t)(s1 + r) * HDd + c * 8, 16);
            }
        }
        cp_commit();
        cp_wait<1>();                      // tile t16 landed
        __syncthreads();

        uint32_t KsB = sb + (uint32_t)((t16 & 1) * STAGE_B);
        uint32_t VsB = KsB + KV_STG;

        // ---- scores = Q' @ K^T (Q pre-scaled by 0.125*log2e) ----
        float sc[8][4];
#pragma unroll
        for (int nt = 0; nt < 8; nt++)
#pragma unroll
            for (int cc = 0; cc < 4; cc++) sc[nt][cc] = 0.f;

#pragma unroll
        for (int kk = 0; kk < 4; kk++) {
#pragma unroll
            for (int p = 0; p < 4; p++) {
                uint32_t r0, r1, r2, r3;
                ldsm_x4(r0, r1, r2, r3,
                        KsB + (uint32_t)((p * 16 + brow) * KV_B + kk * 32 + bkq));
                mma_f16(sc[2 * p],     qf[kk], r0, r1);
                mma_f16(sc[2 * p + 1], qf[kk], r2, r3);
            }
        }

        // ---- probs: p = 2^(sc + mask'), 2-at-a-time in half2 ----
        const float* mk = msk + t16 * 64;
        uint32_t pa[4][4];
#pragma unroll
        for (int kk = 0; kk < 4; kk++) {
            int n0t = 2 * kk, n1t = 2 * kk + 1;
            float a0 = mk[n0t * 8 + 2 * t], a1 = mk[n0t * 8 + 2 * t + 1];
            float b0 = mk[n1t * 8 + 2 * t], b1 = mk[n1t * 8 + 2 * t + 1];
            pa[kk][0] = ex2_h2(pack_h2(sc[n0t][0] + a0, sc[n0t][1] + a1));
            pa[kk][1] = ex2_h2(pack_h2(sc[n0t][2] + a0, sc[n0t][3] + a1));
            pa[kk][2] = ex2_h2(pack_h2(sc[n1t][0] + b0, sc[n1t][1] + b1));
            pa[kk][3] = ex2_h2(pack_h2(sc[n1t][2] + b0, sc[n1t][3] + b1));
        }

        // ---- row sums via HMMA against ones + oacc += P @ V ----
#pragma unroll
        for (int kk = 0; kk < 4; kk++) {
            mma_f16(ls, pa[kk], ONES_H2, ONES_H2);
#pragma unroll
            for (int p = 0; p < 4; p++) {
                uint32_t r0, r1, r2, r3;
                ldsm_x4_t(r0, r1, r2, r3,
                          VsB + (uint32_t)((kk * 16 + vrow) * KV_B + p * 32 + vkq));
                mma_f16(oacc[2 * p],     pa[kk], r0, r1);
                mma_f16(oacc[2 * p + 1], pa[kk], r2, r3);
            }
        }
    }

    // ---- epilogue (fp32 out) ----
    float iA = 1.f / ls[0];
    float iB = 1.f / ls[2];
    int rA = q0 + w * 16 + g;
#pragma unroll
    for (int nt = 0; nt < 8; nt++) {
        int col = h * 64 + nt * 8 + 2 * t;
        *(float2*)&out[((size_t)b * KQd + rA) * Hd + col] =
            make_float2(oacc[nt][0] * iA, oacc[nt][1] * iA);
        *(float2*)&out[((size_t)b * KQd + rA + 8) * Hd + col] =
            make_float2(oacc[nt][2] * iB, oacc[nt][3] * iB);
    }
}

// ---------------------------------------------------------------------------
extern "C" void kernel_launch(void* const* d_in, const int* in_sizes, int n_in,
                              void* d_out, int out_size)
{
    const float* hidden = (const float*)d_in[0];
    const float* mask   = (const float*)d_in[1];
    const int*   remain = (const int*)d_in[2];
    const float* Wq = (const float*)d_in[3];
    const float* bq = (const float*)d_in[4];
    const float* Wk = (const float*)d_in[5];
    const float* bk = (const float*)d_in[6];
    const float* Wv = (const float*)d_in[7];
    const float* bv = (const float*)d_in[8];
    float* out = (float*)d_out;

    cudaFuncSetAttribute(gemm_qkv_f16,
                         cudaFuncAttributeMaxDynamicSharedMemorySize, GEMM_SMEM);
    cudaFuncSetAttribute(attn_f16,
                         cudaFuncAttributeMaxDynamicSharedMemorySize, ATT_SMEM);

    init_kernel<<<INIT_GRID, 1024>>>(remain, hidden, Wq, Wk, Wv);

    gemm_qkv_f16<<<dim3(20, 8, Bd), 256, GEMM_SMEM>>>(bq, bk, bv);

    attn_f16<<<dim3(KQd / 64, NHd, Bd), 128, ATT_SMEM>>>(mask, out);
}